// round 3
// baseline (speedup 1.0000x reference)
#include <cuda_runtime.h>
#include <cuda_bf16.h>

#define D_MODEL 1536
#define T_TOT   2304
#define S_HID   2048
#define S_ENC   256
#define NH      24
#define HD      64

// Scratch (allocation-free rule: __device__ globals)
__device__ float g_Q[NH * T_TOT * HD];   // [h][t][d]
__device__ float g_K[NH * T_TOT * HD];
__device__ float g_V[NH * T_TOT * HD];
__device__ float g_O[S_HID * D_MODEL];   // [t][h*64+d]

// ---------------------------------------------------------------------------
// GEMM: C[M,1536] = A[M,1536] @ W[1536,1536]^T + bias
// blockIdx.z selects one of up to 3 (W, bias, out) triples.
// headmode=1: write C[m][n] to out[((n>>6)*T_TOT + toff + m)*64 + (n&63)]
// headmode=0: write C[m][n] to out[m*1536 + n]
// 128x128x16 tile, 256 threads, 8x8 per thread, interleaved ownership.
// Register double-buffer: next k-tile LDGs issue before the FFMA body.
// ---------------------------------------------------------------------------
__global__ __launch_bounds__(256, 2)
void gemm_kernel(const float* __restrict__ A, int M,
                 const float* __restrict__ W0, const float* __restrict__ B0, float* O0,
                 const float* __restrict__ W1, const float* __restrict__ B1, float* O1,
                 const float* __restrict__ W2, const float* __restrict__ B2, float* O2,
                 int headmode, int toff)
{
    const float* W  = W0; const float* Bv = B0; float* Oo = O0;
    if (blockIdx.z == 1)      { W = W1; Bv = B1; Oo = O1; }
    else if (blockIdx.z == 2) { W = W2; Bv = B2; Oo = O2; }

    __shared__ float As[128][20];   // stride 20 words: float4-aligned, 2-way max conflict
    __shared__ float Bs[128][20];

    int tid = threadIdx.x;
    int tx  = tid & 15;      // output col group
    int ty  = tid >> 4;      // output row group
    int m0  = blockIdx.y * 128;
    int n0  = blockIdx.x * 128;

    int lrow = tid >> 2;          // 0..63 (tile row for loads)
    int lc4  = (tid & 3) * 4;     // 0,4,8,12 (k-chunk)

    const float* Ap = A + (long)(m0 + lrow) * D_MODEL + lc4;
    const float* Wp = W + (long)(n0 + lrow) * D_MODEL + lc4;

    float acc[8][8];
    #pragma unroll
    for (int i = 0; i < 8; i++)
        #pragma unroll
        for (int j = 0; j < 8; j++) acc[i][j] = 0.f;

    // preload k-tile 0
    float4 av0 = *(const float4*)(Ap);
    float4 av1 = *(const float4*)(Ap + 64 * D_MODEL);
    float4 bv0 = *(const float4*)(Wp);
    float4 bv1 = *(const float4*)(Wp + 64 * D_MODEL);

    for (int k0 = 0; k0 < D_MODEL; k0 += 16) {
        *(float4*)&As[lrow][lc4]      = av0;
        *(float4*)&As[lrow + 64][lc4] = av1;
        *(float4*)&Bs[lrow][lc4]      = bv0;
        *(float4*)&Bs[lrow + 64][lc4] = bv1;
        __syncthreads();

        if (k0 + 16 < D_MODEL) {    // prefetch next tile; overlaps FFMA body
            av0 = *(const float4*)(Ap + k0 + 16);
            av1 = *(const float4*)(Ap + 64 * D_MODEL + k0 + 16);
            bv0 = *(const float4*)(Wp + k0 + 16);
            bv1 = *(const float4*)(Wp + 64 * D_MODEL + k0 + 16);
        }

        #pragma unroll
        for (int kk = 0; kk < 16; kk++) {
            float a[8], b[8];
            #pragma unroll
            for (int i = 0; i < 8; i++) a[i] = As[ty + 16 * i][kk];
            #pragma unroll
            for (int j = 0; j < 8; j++) b[j] = Bs[tx + 16 * j][kk];
            #pragma unroll
            for (int i = 0; i < 8; i++)
                #pragma unroll
                for (int j = 0; j < 8; j++)
                    acc[i][j] += a[i] * b[j];
        }
        __syncthreads();
    }

    #pragma unroll
    for (int i = 0; i < 8; i++) {
        int m = m0 + ty + 16 * i;
        #pragma unroll
        for (int j = 0; j < 8; j++) {
            int n = n0 + tx + 16 * j;
            float v = acc[i][j] + Bv[n];
            if (headmode) {
                Oo[((long)(n >> 6) * T_TOT + toff + m) * HD + (n & 63)] = v;
            } else {
                Oo[(long)m * D_MODEL + n] = v;
            }
        }
    }
}

// ---------------------------------------------------------------------------
// Per-head RMSNorm over last dim (64). One warp per row.
// buf layout [h][T_TOT][64]; valid t in [0, Tcnt); w = (t < tsplit) ? w0 : w1
// ---------------------------------------------------------------------------
__global__ void rmsnorm_kernel(float* __restrict__ buf,
                               const float* __restrict__ w0,
                               const float* __restrict__ w1,
                               int Tcnt, int tsplit, int nrows)
{
    int row = blockIdx.x * (blockDim.x >> 5) + (threadIdx.x >> 5);
    if (row >= nrows) return;
    int lane = threadIdx.x & 31;
    int h = row / Tcnt;
    int t = row - h * Tcnt;
    float* p = buf + ((long)h * T_TOT + t) * HD + lane * 2;
    float2 v = *(float2*)p;
    float ss = v.x * v.x + v.y * v.y;
    #pragma unroll
    for (int o = 16; o > 0; o >>= 1) ss += __shfl_xor_sync(0xffffffffu, ss, o);
    float inv = rsqrtf(ss * (1.0f / 64.0f) + 1e-6f);
    const float* w = (t < tsplit) ? w0 : w1;
    v.x *= inv * w[lane * 2];
    v.y *= inv * w[lane * 2 + 1];
    *(float2*)p = v;
}

// ---------------------------------------------------------------------------
// Flash attention fp32: queries 0..2047, keys/values 0..2303, per head.
// BQ=64, BKV=32, 256 threads (16x16), per thread: 4 q-rows x (2 keys | 4 d).
// K/V tiles register double-buffered: next tile LDGs overlap compute body.
// ---------------------------------------------------------------------------
__global__ __launch_bounds__(256)
void attn_kernel(const float* __restrict__ Q, const float* __restrict__ K,
                 const float* __restrict__ V, const float* __restrict__ mask,
                 float* __restrict__ O)
{
    __shared__ float Qs[64][68];
    __shared__ float Ks[32][68];
    __shared__ float Vs[32][68];
    __shared__ float Ps[32][68];

    int h  = blockIdx.y;
    int q0 = blockIdx.x * 64;
    int tid = threadIdx.x;
    int tx = tid & 15, ty = tid >> 4;
    const float scale = 0.125f;   // 64^-0.5

    const float* Qh = Q + ((long)h * T_TOT + q0) * HD;
    const float* Kh = K + (long)h * T_TOT * HD;
    const float* Vh = V + (long)h * T_TOT * HD;

    #pragma unroll
    for (int it = 0; it < 4; it++) {
        int idx = tid + it * 256;
        int r = idx >> 4, c4 = (idx & 15) * 4;
        float4 v4 = *(const float4*)(Qh + r * 64 + c4);
        v4.x *= scale; v4.y *= scale; v4.z *= scale; v4.w *= scale;
        *(float4*)&Qs[r][c4] = v4;
    }

    float m_i[4], l_i[4], acc[4][4];
    #pragma unroll
    for (int i = 0; i < 4; i++) {
        m_i[i] = -1e30f; l_i[i] = 0.f;
        acc[i][0] = acc[i][1] = acc[i][2] = acc[i][3] = 0.f;
    }

    // loader geometry: rows r0=tid>>4 (+16), k-chunk c4=(tid&15)*4
    int lr = tid >> 4;           // 0..15
    int lc = (tid & 15) * 4;     // 0..60

    // preload K/V tile 0 into registers
    float4 kr0 = *(const float4*)(Kh + (long)lr * 64 + lc);
    float4 kr1 = *(const float4*)(Kh + (long)(lr + 16) * 64 + lc);
    float4 vr0 = *(const float4*)(Vh + (long)lr * 64 + lc);
    float4 vr1 = *(const float4*)(Vh + (long)(lr + 16) * 64 + lc);

    for (int k0 = 0; k0 < T_TOT; k0 += 32) {
        __syncthreads();   // prev PV done before overwriting K/V tiles
        *(float4*)&Ks[lr][lc]      = kr0;
        *(float4*)&Ks[lr + 16][lc] = kr1;
        *(float4*)&Vs[lr][lc]      = vr0;
        *(float4*)&Vs[lr + 16][lc] = vr1;
        __syncthreads();

        if (k0 + 32 < T_TOT) {   // prefetch next K/V tile; overlaps compute
            long base = (long)(k0 + 32 + lr) * 64 + lc;
            kr0 = *(const float4*)(Kh + base);
            kr1 = *(const float4*)(Kh + base + 16 * 64);
            vr0 = *(const float4*)(Vh + base);
            vr1 = *(const float4*)(Vh + base + 16 * 64);
        }

        // S = (Q*scale) @ K^T   -> s[4 rows][2 keys]
        float s[4][2];
        #pragma unroll
        for (int i = 0; i < 4; i++) { s[i][0] = 0.f; s[i][1] = 0.f; }
        #pragma unroll
        for (int d4 = 0; d4 < 16; d4++) {
            float4 b0 = *(float4*)&Ks[tx][d4 * 4];
            float4 b1 = *(float4*)&Ks[tx + 16][d4 * 4];
            #pragma unroll
            for (int i = 0; i < 4; i++) {
                float4 a = *(float4*)&Qs[ty + 16 * i][d4 * 4];
                s[i][0] += a.x * b0.x + a.y * b0.y + a.z * b0.z + a.w * b0.w;
                s[i][1] += a.x * b1.x + a.y * b1.y + a.z * b1.z + a.w * b1.w;
            }
        }

        float mk0 = mask[k0 + tx];
        float mk1 = mask[k0 + tx + 16];

        // online softmax per row (row stats shared across 16-lane tx group)
        #pragma unroll
        for (int i = 0; i < 4; i++) {
            s[i][0] += mk0; s[i][1] += mk1;
            float rm = fmaxf(s[i][0], s[i][1]);
            #pragma unroll
            for (int o = 8; o > 0; o >>= 1) rm = fmaxf(rm, __shfl_xor_sync(0xffffffffu, rm, o));
            float mn = fmaxf(m_i[i], rm);
            float corr = __expf(m_i[i] - mn);
            s[i][0] = __expf(s[i][0] - mn);
            s[i][1] = __expf(s[i][1] - mn);
            float rs = s[i][0] + s[i][1];
            #pragma unroll
            for (int o = 8; o > 0; o >>= 1) rs += __shfl_xor_sync(0xffffffffu, rs, o);
            l_i[i] = l_i[i] * corr + rs;
            m_i[i] = mn;
            acc[i][0] *= corr; acc[i][1] *= corr; acc[i][2] *= corr; acc[i][3] *= corr;
            Ps[tx][ty + 16 * i]      = s[i][0];   // P stored [key][q]
            Ps[tx + 16][ty + 16 * i] = s[i][1];
        }
        __syncthreads();

        // O += P @ V
        #pragma unroll
        for (int kk = 0; kk < 32; kk++) {
            float4 b = *(float4*)&Vs[kk][tx * 4];
            #pragma unroll
            for (int i = 0; i < 4; i++) {
                float a = Ps[kk][ty + 16 * i];
                acc[i][0] += a * b.x;
                acc[i][1] += a * b.y;
                acc[i][2] += a * b.z;
                acc[i][3] += a * b.w;
            }
        }
    }

    #pragma unroll
    for (int i = 0; i < 4; i++) {
        float inv = 1.0f / l_i[i];
        int row = q0 + ty + 16 * i;
        float4 ov;
        ov.x = acc[i][0] * inv; ov.y = acc[i][1] * inv;
        ov.z = acc[i][2] * inv; ov.w = acc[i][3] * inv;
        *(float4*)(O + (long)row * D_MODEL + h * HD + tx * 4) = ov;
    }
}

// ---------------------------------------------------------------------------
extern "C" void kernel_launch(void* const* d_in, const int* in_sizes, int n_in,
                              void* d_out, int out_size)
{
    const float* hid  = (const float*)d_in[0];
    const float* enc  = (const float*)d_in[1];
    const float* mask = (const float*)d_in[2];
    const float* Wq   = (const float*)d_in[3];
    const float* bq   = (const float*)d_in[4];
    const float* Wk   = (const float*)d_in[5];
    const float* bk   = (const float*)d_in[6];
    const float* Wv   = (const float*)d_in[7];
    const float* bv   = (const float*)d_in[8];
    const float* nq   = (const float*)d_in[9];
    const float* nk   = (const float*)d_in[10];
    // d_in[11], d_in[12]: add_q_proj (dead: encoder queries' output is discarded)
    const float* Wak  = (const float*)d_in[13];
    const float* bak  = (const float*)d_in[14];
    const float* Wav  = (const float*)d_in[15];
    const float* bav  = (const float*)d_in[16];
    // d_in[17]: norm_added_q (dead)
    const float* nak  = (const float*)d_in[18];
    const float* Wo   = (const float*)d_in[19];
    const float* bo   = (const float*)d_in[20];
    // d_in[21], d_in[22]: to_add_out (dead), d_in[23], d_in[24]: scalars
    float* out = (float*)d_out;

    float *Qb, *Kb, *Vb, *Ob;
    cudaGetSymbolAddress((void**)&Qb, g_Q);
    cudaGetSymbolAddress((void**)&Kb, g_K);
    cudaGetSymbolAddress((void**)&Vb, g_V);
    cudaGetSymbolAddress((void**)&Ob, g_O);

    // 1) hidden-stream Q/K/V projections (head-split layout)
    {
        dim3 grid(D_MODEL / 128, S_HID / 128, 3);
        gemm_kernel<<<grid, 256>>>(hid, S_HID,
                                   Wq, bq, Qb,
                                   Wk, bk, Kb,
                                   Wv, bv, Vb,
                                   1, 0);
    }
    // 2) encoder-stream K/V projections appended at t offset 2048
    {
        dim3 grid(D_MODEL / 128, S_ENC / 128, 2);
        gemm_kernel<<<grid, 256>>>(enc, S_ENC,
                                   Wak, bak, Kb,
                                   Wav, bav, Vb,
                                   Wak, bak, Kb,   // unused slot
                                   1, S_HID);
    }
    // 3) RMSNorm on Q (hidden only) and K (hidden + encoder, different weights)
    {
        int rowsQ = NH * S_HID;
        rmsnorm_kernel<<<(rowsQ + 7) / 8, 256>>>(Qb, nq, nq, S_HID, S_HID, rowsQ);
        int rowsK = NH * T_TOT;
        rmsnorm_kernel<<<(rowsK + 7) / 8, 256>>>(Kb, nk, nak, T_TOT, S_HID, rowsK);
    }
    // 4) attention (2048 queries x 2304 keys, 24 heads)
    {
        dim3 grid(S_HID / 64, NH);
        attn_kernel<<<grid, 256>>>(Qb, Kb, Vb, mask, Ob);
    }
    // 5) output projection -> d_out
    {
        dim3 grid(D_MODEL / 128, S_HID / 128, 1);
        gemm_kernel<<<grid, 256>>>(Ob, S_HID,
                                   Wo, bo, out,
                                   Wo, bo, out,   // unused slots
                                   Wo, bo, out,
                                   0, 0);
    }
}

// round 4
// speedup vs baseline: 1.5656x; 1.5656x over previous
#include <cuda_runtime.h>
#include <cuda_bf16.h>
#include <cstdint>

#define D_MODEL 1536
#define T_TOT   2304
#define S_HID   2048
#define S_ENC   256
#define NH      24
#define HD      64

// Scratch (allocation-free rule: __device__ globals)
__device__ float g_Q[NH * T_TOT * HD];   // [h][t][d]
__device__ float g_K[NH * T_TOT * HD];
__device__ float g_V[NH * T_TOT * HD];
__device__ float g_O[S_HID * D_MODEL];   // [t][h*64+d]

__device__ __forceinline__ uint32_t f2tf(float x) {
    uint32_t r;
    asm("cvt.rna.tf32.f32 %0, %1;" : "=r"(r) : "f"(x));
    return r;
}

// ---------------------------------------------------------------------------
// TF32 tensor-core GEMM: C[M,1536] = A[M,1536] @ W[1536,1536]^T + bias
// blockIdx.z selects one of up to 3 (W, bias, out) triples.
// headmode=1: C[m][n] -> out[((n>>6)*T_TOT + toff + m)*64 + (n&63)]
// headmode=0: C[m][n] -> out[m*1536 + n]
// Block tile 128x128x32, 256 threads = 8 warps (2x4), warp tile 64x32.
// mma.sync.m16n8k8 tf32; smem holds operands in fragment-major layout so the
// hot loop reads A-frags with LDS.128 and B-frags with LDS.64, conflict-free.
// ---------------------------------------------------------------------------
__global__ __launch_bounds__(256, 1)
void gemm_kernel(const float* __restrict__ A, int M,
                 const float* __restrict__ W0, const float* __restrict__ B0, float* O0,
                 const float* __restrict__ W1, const float* __restrict__ B1, float* O1,
                 const float* __restrict__ W2, const float* __restrict__ B2, float* O2,
                 int headmode, int toff)
{
    const float* W  = W0; const float* Bv = B0; float* Oo = O0;
    if (blockIdx.z == 1)      { W = W1; Bv = B1; Oo = O1; }
    else if (blockIdx.z == 2) { W = W2; Bv = B2; Oo = O2; }

    // As: [kb 0..3][mt 0..7][lane 0..31][ri 0..3]  (16 KB)
    // Bs: [kb 0..3][nt 0..15][lane 0..31][ri 0..1] (16 KB)
    __shared__ uint32_t As[4096];
    __shared__ uint32_t Bs[4096];

    int tid    = threadIdx.x;
    int lane   = tid & 31;
    int wid    = tid >> 5;
    int warp_m = wid >> 2;   // 0..1  (64-row slab)
    int warp_n = wid & 3;    // 0..3  (32-col slab)
    int m0 = blockIdx.y * 128;
    int n0 = blockIdx.x * 128;

    // Loader geometry: row lr = tid>>1 (0..127), col half lcb = (tid&1)*16
    int lr  = tid >> 1;
    int lcb = (tid & 1) * 16;
    const float* Ap = A + (long)(m0 + lr) * D_MODEL + lcb;
    const float* Wp = W + (long)(n0 + lr) * D_MODEL + lcb;

    // Scatter-index constants for this thread's row
    int mtA = lr >> 4;           // m16 tile
    int gA  = lr & 7;            // lane group
    int hiA = (lr >> 3) & 1;     // +8 row half
    int ntB = lr >> 3;           // n8 tile
    int gB  = lr & 7;

    float acc[4][4][4];
    #pragma unroll
    for (int i = 0; i < 4; i++)
        #pragma unroll
        for (int j = 0; j < 4; j++)
            #pragma unroll
            for (int e = 0; e < 4; e++) acc[i][j][e] = 0.f;

    // preload k-tile 0
    float4 a_pref[4], b_pref[4];
    #pragma unroll
    for (int q = 0; q < 4; q++) {
        a_pref[q] = *(const float4*)(Ap + q * 4);
        b_pref[q] = *(const float4*)(Wp + q * 4);
    }

    for (int k0 = 0; k0 < D_MODEL; k0 += 32) {
        __syncthreads();   // previous iteration's fragment reads complete
        #pragma unroll
        for (int q = 0; q < 4; q++) {
            int kl  = lcb + q * 4;          // local k of first element
            int kb  = kl >> 3;
            int kc2 = (kl >> 2) & 1;
            uint32_t* ap = &As[(((kb * 8 + mtA) * 32 + gA * 4) << 2) + hiA + (kc2 << 1)];
            ap[0]  = f2tf(a_pref[q].x);
            ap[4]  = f2tf(a_pref[q].y);
            ap[8]  = f2tf(a_pref[q].z);
            ap[12] = f2tf(a_pref[q].w);
            uint32_t* bp = &Bs[(((kb * 16 + ntB) * 32 + gB * 4) << 1) + kc2];
            bp[0] = f2tf(b_pref[q].x);
            bp[2] = f2tf(b_pref[q].y);
            bp[4] = f2tf(b_pref[q].z);
            bp[6] = f2tf(b_pref[q].w);
        }
        __syncthreads();

        if (k0 + 32 < D_MODEL) {    // prefetch next k-tile; overlaps MMA body
            #pragma unroll
            for (int q = 0; q < 4; q++) {
                a_pref[q] = *(const float4*)(Ap + k0 + 32 + q * 4);
                b_pref[q] = *(const float4*)(Wp + k0 + 32 + q * 4);
            }
        }

        #pragma unroll
        for (int kb = 0; kb < 4; kb++) {
            uint4 af[4];
            uint2 bf[4];
            #pragma unroll
            for (int i = 0; i < 4; i++)
                af[i] = *(const uint4*)&As[((kb * 8 + warp_m * 4 + i) * 32 + lane) * 4];
            #pragma unroll
            for (int j = 0; j < 4; j++)
                bf[j] = *(const uint2*)&Bs[((kb * 16 + warp_n * 4 + j) * 32 + lane) * 2];
            #pragma unroll
            for (int i = 0; i < 4; i++)
                #pragma unroll
                for (int j = 0; j < 4; j++) {
                    asm volatile(
                        "mma.sync.aligned.m16n8k8.row.col.f32.tf32.tf32.f32 "
                        "{%0,%1,%2,%3}, {%4,%5,%6,%7}, {%8,%9}, {%0,%1,%2,%3};"
                        : "+f"(acc[i][j][0]), "+f"(acc[i][j][1]),
                          "+f"(acc[i][j][2]), "+f"(acc[i][j][3])
                        : "r"(af[i].x), "r"(af[i].y), "r"(af[i].z), "r"(af[i].w),
                          "r"(bf[j].x), "r"(bf[j].y));
                }
        }
    }

    // Epilogue: c0=C[g][2t4], c1=C[g][2t4+1], c2=C[g+8][2t4], c3=C[g+8][2t4+1]
    int g  = lane >> 2;
    int t4 = lane & 3;
    #pragma unroll
    for (int i = 0; i < 4; i++) {
        int r0 = m0 + warp_m * 64 + i * 16 + g;
        #pragma unroll
        for (int j = 0; j < 4; j++) {
            int c0 = n0 + warp_n * 32 + j * 8 + t4 * 2;
            float bv0 = Bv[c0], bv1 = Bv[c0 + 1];
            float2 v0 = make_float2(acc[i][j][0] + bv0, acc[i][j][1] + bv1);
            float2 v1 = make_float2(acc[i][j][2] + bv0, acc[i][j][3] + bv1);
            if (headmode) {
                long hb = (long)(c0 >> 6) * T_TOT + toff;
                *(float2*)&Oo[(hb + r0) * 64 + (c0 & 63)]     = v0;
                *(float2*)&Oo[(hb + r0 + 8) * 64 + (c0 & 63)] = v1;
            } else {
                *(float2*)&Oo[(long)r0 * D_MODEL + c0]       = v0;
                *(float2*)&Oo[(long)(r0 + 8) * D_MODEL + c0] = v1;
            }
        }
    }
}

// ---------------------------------------------------------------------------
// Per-head RMSNorm over last dim (64). One warp per row.
// buf layout [h][T_TOT][64]; valid t in [0, Tcnt); w = (t < tsplit) ? w0 : w1
// ---------------------------------------------------------------------------
__global__ void rmsnorm_kernel(float* __restrict__ buf,
                               const float* __restrict__ w0,
                               const float* __restrict__ w1,
                               int Tcnt, int tsplit, int nrows)
{
    int row = blockIdx.x * (blockDim.x >> 5) + (threadIdx.x >> 5);
    if (row >= nrows) return;
    int lane = threadIdx.x & 31;
    int h = row / Tcnt;
    int t = row - h * Tcnt;
    float* p = buf + ((long)h * T_TOT + t) * HD + lane * 2;
    float2 v = *(float2*)p;
    float ss = v.x * v.x + v.y * v.y;
    #pragma unroll
    for (int o = 16; o > 0; o >>= 1) ss += __shfl_xor_sync(0xffffffffu, ss, o);
    float inv = rsqrtf(ss * (1.0f / 64.0f) + 1e-6f);
    const float* w = (t < tsplit) ? w0 : w1;
    v.x *= inv * w[lane * 2];
    v.y *= inv * w[lane * 2 + 1];
    *(float2*)p = v;
}

// ---------------------------------------------------------------------------
// Flash attention fp32: queries 0..2047, keys/values 0..2303, per head.
// BQ=64, BKV=32, 256 threads (16x16), per thread: 4 q-rows x (2 keys | 4 d).
// K/V tiles register double-buffered: next tile LDGs overlap compute body.
// ---------------------------------------------------------------------------
__global__ __launch_bounds__(256)
void attn_kernel(const float* __restrict__ Q, const float* __restrict__ K,
                 const float* __restrict__ V, const float* __restrict__ mask,
                 float* __restrict__ O)
{
    __shared__ float Qs[64][68];
    __shared__ float Ks[32][68];
    __shared__ float Vs[32][68];
    __shared__ float Ps[32][68];

    int h  = blockIdx.y;
    int q0 = blockIdx.x * 64;
    int tid = threadIdx.x;
    int tx = tid & 15, ty = tid >> 4;
    const float scale = 0.125f;   // 64^-0.5

    const float* Qh = Q + ((long)h * T_TOT + q0) * HD;
    const float* Kh = K + (long)h * T_TOT * HD;
    const float* Vh = V + (long)h * T_TOT * HD;

    #pragma unroll
    for (int it = 0; it < 4; it++) {
        int idx = tid + it * 256;
        int r = idx >> 4, c4 = (idx & 15) * 4;
        float4 v4 = *(const float4*)(Qh + r * 64 + c4);
        v4.x *= scale; v4.y *= scale; v4.z *= scale; v4.w *= scale;
        *(float4*)&Qs[r][c4] = v4;
    }

    float m_i[4], l_i[4], acc[4][4];
    #pragma unroll
    for (int i = 0; i < 4; i++) {
        m_i[i] = -1e30f; l_i[i] = 0.f;
        acc[i][0] = acc[i][1] = acc[i][2] = acc[i][3] = 0.f;
    }

    int lr = tid >> 4;           // 0..15
    int lc = (tid & 15) * 4;     // 0..60

    // preload K/V tile 0 into registers
    float4 kr0 = *(const float4*)(Kh + (long)lr * 64 + lc);
    float4 kr1 = *(const float4*)(Kh + (long)(lr + 16) * 64 + lc);
    float4 vr0 = *(const float4*)(Vh + (long)lr * 64 + lc);
    float4 vr1 = *(const float4*)(Vh + (long)(lr + 16) * 64 + lc);

    for (int k0 = 0; k0 < T_TOT; k0 += 32) {
        __syncthreads();   // prev PV done before overwriting K/V tiles
        *(float4*)&Ks[lr][lc]      = kr0;
        *(float4*)&Ks[lr + 16][lc] = kr1;
        *(float4*)&Vs[lr][lc]      = vr0;
        *(float4*)&Vs[lr + 16][lc] = vr1;
        __syncthreads();

        if (k0 + 32 < T_TOT) {   // prefetch next K/V tile; overlaps compute
            long base = (long)(k0 + 32 + lr) * 64 + lc;
            kr0 = *(const float4*)(Kh + base);
            kr1 = *(const float4*)(Kh + base + 16 * 64);
            vr0 = *(const float4*)(Vh + base);
            vr1 = *(const float4*)(Vh + base + 16 * 64);
        }

        // S = (Q*scale) @ K^T   -> s[4 rows][2 keys]
        float s[4][2];
        #pragma unroll
        for (int i = 0; i < 4; i++) { s[i][0] = 0.f; s[i][1] = 0.f; }
        #pragma unroll
        for (int d4 = 0; d4 < 16; d4++) {
            float4 b0 = *(float4*)&Ks[tx][d4 * 4];
            float4 b1 = *(float4*)&Ks[tx + 16][d4 * 4];
            #pragma unroll
            for (int i = 0; i < 4; i++) {
                float4 a = *(float4*)&Qs[ty + 16 * i][d4 * 4];
                s[i][0] += a.x * b0.x + a.y * b0.y + a.z * b0.z + a.w * b0.w;
                s[i][1] += a.x * b1.x + a.y * b1.y + a.z * b1.z + a.w * b1.w;
            }
        }

        float mk0 = mask[k0 + tx];
        float mk1 = mask[k0 + tx + 16];

        // online softmax per row (row stats shared across 16-lane tx group)
        #pragma unroll
        for (int i = 0; i < 4; i++) {
            s[i][0] += mk0; s[i][1] += mk1;
            float rm = fmaxf(s[i][0], s[i][1]);
            #pragma unroll
            for (int o = 8; o > 0; o >>= 1) rm = fmaxf(rm, __shfl_xor_sync(0xffffffffu, rm, o));
            float mn = fmaxf(m_i[i], rm);
            float corr = __expf(m_i[i] - mn);
            s[i][0] = __expf(s[i][0] - mn);
            s[i][1] = __expf(s[i][1] - mn);
            float rs = s[i][0] + s[i][1];
            #pragma unroll
            for (int o = 8; o > 0; o >>= 1) rs += __shfl_xor_sync(0xffffffffu, rs, o);
            l_i[i] = l_i[i] * corr + rs;
            m_i[i] = mn;
            acc[i][0] *= corr; acc[i][1] *= corr; acc[i][2] *= corr; acc[i][3] *= corr;
            Ps[tx][ty + 16 * i]      = s[i][0];   // P stored [key][q]
            Ps[tx + 16][ty + 16 * i] = s[i][1];
        }
        __syncthreads();

        // O += P @ V
        #pragma unroll
        for (int kk = 0; kk < 32; kk++) {
            float4 b = *(float4*)&Vs[kk][tx * 4];
            #pragma unroll
            for (int i = 0; i < 4; i++) {
                float a = Ps[kk][ty + 16 * i];
                acc[i][0] += a * b.x;
                acc[i][1] += a * b.y;
                acc[i][2] += a * b.z;
                acc[i][3] += a * b.w;
            }
        }
    }

    #pragma unroll
    for (int i = 0; i < 4; i++) {
        float inv = 1.0f / l_i[i];
        int row = q0 + ty + 16 * i;
        float4 ov;
        ov.x = acc[i][0] * inv; ov.y = acc[i][1] * inv;
        ov.z = acc[i][2] * inv; ov.w = acc[i][3] * inv;
        *(float4*)(O + (long)row * D_MODEL + h * HD + tx * 4) = ov;
    }
}

// ---------------------------------------------------------------------------
extern "C" void kernel_launch(void* const* d_in, const int* in_sizes, int n_in,
                              void* d_out, int out_size)
{
    const float* hid  = (const float*)d_in[0];
    const float* enc  = (const float*)d_in[1];
    const float* mask = (const float*)d_in[2];
    const float* Wq   = (const float*)d_in[3];
    const float* bq   = (const float*)d_in[4];
    const float* Wk   = (const float*)d_in[5];
    const float* bk   = (const float*)d_in[6];
    const float* Wv   = (const float*)d_in[7];
    const float* bv   = (const float*)d_in[8];
    const float* nq   = (const float*)d_in[9];
    const float* nk   = (const float*)d_in[10];
    // d_in[11], d_in[12]: add_q_proj (dead: encoder queries' output is discarded)
    const float* Wak  = (const float*)d_in[13];
    const float* bak  = (const float*)d_in[14];
    const float* Wav  = (const float*)d_in[15];
    const float* bav  = (const float*)d_in[16];
    // d_in[17]: norm_added_q (dead)
    const float* nak  = (const float*)d_in[18];
    const float* Wo   = (const float*)d_in[19];
    const float* bo   = (const float*)d_in[20];
    // d_in[21], d_in[22]: to_add_out (dead), d_in[23], d_in[24]: scalars
    float* out = (float*)d_out;

    float *Qb, *Kb, *Vb, *Ob;
    cudaGetSymbolAddress((void**)&Qb, g_Q);
    cudaGetSymbolAddress((void**)&Kb, g_K);
    cudaGetSymbolAddress((void**)&Vb, g_V);
    cudaGetSymbolAddress((void**)&Ob, g_O);

    // 1) hidden-stream Q/K/V projections (head-split layout)
    {
        dim3 grid(D_MODEL / 128, S_HID / 128, 3);
        gemm_kernel<<<grid, 256>>>(hid, S_HID,
                                   Wq, bq, Qb,
                                   Wk, bk, Kb,
                                   Wv, bv, Vb,
                                   1, 0);
    }
    // 2) encoder-stream K/V projections appended at t offset 2048
    {
        dim3 grid(D_MODEL / 128, S_ENC / 128, 2);
        gemm_kernel<<<grid, 256>>>(enc, S_ENC,
                                   Wak, bak, Kb,
                                   Wav, bav, Vb,
                                   Wak, bak, Kb,   // unused slot
                                   1, S_HID);
    }
    // 3) RMSNorm on Q (hidden only) and K (hidden + encoder, different weights)
    {
        int rowsQ = NH * S_HID;
        rmsnorm_kernel<<<(rowsQ + 7) / 8, 256>>>(Qb, nq, nq, S_HID, S_HID, rowsQ);
        int rowsK = NH * T_TOT;
        rmsnorm_kernel<<<(rowsK + 7) / 8, 256>>>(Kb, nk, nak, T_TOT, S_HID, rowsK);
    }
    // 4) attention (2048 queries x 2304 keys, 24 heads)
    {
        dim3 grid(S_HID / 64, NH);
        attn_kernel<<<grid, 256>>>(Qb, Kb, Vb, mask, Ob);
    }
    // 5) output projection -> d_out
    {
        dim3 grid(D_MODEL / 128, S_HID / 128, 1);
        gemm_kernel<<<grid, 256>>>(Ob, S_HID,
                                   Wo, bo, out,
                                   Wo, bo, out,   // unused slots
                                   Wo, bo, out,
                                   0, 0);
    }
}

// round 11
// speedup vs baseline: 1.9123x; 1.2215x over previous
#include <cuda_runtime.h>
#include <cuda_bf16.h>
#include <cstdint>

#define D_MODEL 1536
#define T_TOT   2304
#define S_HID   2048
#define S_ENC   256
#define NH      24
#define HD      64

// Scratch (allocation-free rule: __device__ globals)
__device__ float g_Q[NH * T_TOT * HD];   // [h][t][d]
__device__ float g_K[NH * T_TOT * HD];
__device__ float g_V[NH * T_TOT * HD];
__device__ float g_O[S_HID * D_MODEL];   // [t][h*64+d]

__device__ __forceinline__ uint32_t f2tf(float x) {
    uint32_t r;
    asm("cvt.rna.tf32.f32 %0, %1;" : "=r"(r) : "f"(x));
    return r;
}

#define MMA_TF32(d, a, b) \
    asm volatile( \
        "mma.sync.aligned.m16n8k8.row.col.f32.tf32.tf32.f32 " \
        "{%0,%1,%2,%3}, {%4,%5,%6,%7}, {%8,%9}, {%0,%1,%2,%3};" \
        : "+f"((d)[0]), "+f"((d)[1]), "+f"((d)[2]), "+f"((d)[3]) \
        : "r"((a).x), "r"((a).y), "r"((a).z), "r"((a).w), \
          "r"((b).x), "r"((b).y))

// ---------------------------------------------------------------------------
// TF32 tensor-core GEMM: C[M,1536] = A[M,1536] @ W[1536,1536]^T + bias
// blockIdx.z selects one of up to 5 (W, bias, out) triples.
// z<3 reads A (M rows); z>=3 reads A2 (S_ENC rows; y>=2 blocks early-exit)
// and writes at t-offset S_HID in headmode layout.
// headmode=1: C[m][n] -> out[((n>>6)*T_TOT + toff + m)*64 + (n&63)]
// headmode=0: C[m][n] -> out[m*1536 + n]
// ---------------------------------------------------------------------------
__global__ __launch_bounds__(256, 1)
void gemm_kernel(const float* __restrict__ A, const float* __restrict__ A2,
                 const float* __restrict__ W0, const float* __restrict__ B0, float* O0,
                 const float* __restrict__ W1, const float* __restrict__ B1, float* O1,
                 const float* __restrict__ W2, const float* __restrict__ B2, float* O2,
                 const float* __restrict__ W3, const float* __restrict__ B3, float* O3,
                 const float* __restrict__ W4, const float* __restrict__ B4, float* O4,
                 int headmode)
{
    const float* W  = W0; const float* Bv = B0; float* Oo = O0;
    const float* Asrc = A;
    int toff = 0;
    int z = blockIdx.z;
    if (z == 1)      { W = W1; Bv = B1; Oo = O1; }
    else if (z == 2) { W = W2; Bv = B2; Oo = O2; }
    else if (z >= 3) {
        if (blockIdx.y >= S_ENC / 128) return;   // encoder stream: 2 y-blocks only
        Asrc = A2; toff = S_HID;
        if (z == 3) { W = W3; Bv = B3; Oo = O3; }
        else        { W = W4; Bv = B4; Oo = O4; }
    }

    __shared__ uint32_t As[4096];
    __shared__ uint32_t Bs[4096];

    int tid    = threadIdx.x;
    int lane   = tid & 31;
    int wid    = tid >> 5;
    int warp_m = wid >> 2;
    int warp_n = wid & 3;
    int m0 = blockIdx.y * 128;
    int n0 = blockIdx.x * 128;

    int lr  = tid >> 1;
    int lcb = (tid & 1) * 16;
    const float* Ap = Asrc + (long)(m0 + lr) * D_MODEL + lcb;
    const float* Wp = W + (long)(n0 + lr) * D_MODEL + lcb;

    int mtA = lr >> 4;
    int gA  = lr & 7;
    int hiA = (lr >> 3) & 1;
    int ntB = lr >> 3;
    int gB  = lr & 7;

    float acc[4][4][4];
    #pragma unroll
    for (int i = 0; i < 4; i++)
        #pragma unroll
        for (int j = 0; j < 4; j++)
            #pragma unroll
            for (int e = 0; e < 4; e++) acc[i][j][e] = 0.f;

    float4 a_pref[4], b_pref[4];
    #pragma unroll
    for (int q = 0; q < 4; q++) {
        a_pref[q] = *(const float4*)(Ap + q * 4);
        b_pref[q] = *(const float4*)(Wp + q * 4);
    }

    for (int k0 = 0; k0 < D_MODEL; k0 += 32) {
        __syncthreads();
        #pragma unroll
        for (int q = 0; q < 4; q++) {
            int kl  = lcb + q * 4;
            int kb  = kl >> 3;
            int kc2 = (kl >> 2) & 1;
            uint32_t* ap = &As[(((kb * 8 + mtA) * 32 + gA * 4) << 2) + hiA + (kc2 << 1)];
            ap[0]  = f2tf(a_pref[q].x);
            ap[4]  = f2tf(a_pref[q].y);
            ap[8]  = f2tf(a_pref[q].z);
            ap[12] = f2tf(a_pref[q].w);
            uint32_t* bp = &Bs[(((kb * 16 + ntB) * 32 + gB * 4) << 1) + kc2];
            bp[0] = f2tf(b_pref[q].x);
            bp[2] = f2tf(b_pref[q].y);
            bp[4] = f2tf(b_pref[q].z);
            bp[6] = f2tf(b_pref[q].w);
        }
        __syncthreads();

        if (k0 + 32 < D_MODEL) {
            #pragma unroll
            for (int q = 0; q < 4; q++) {
                a_pref[q] = *(const float4*)(Ap + k0 + 32 + q * 4);
                b_pref[q] = *(const float4*)(Wp + k0 + 32 + q * 4);
            }
        }

        #pragma unroll
        for (int kb = 0; kb < 4; kb++) {
            uint4 af[4];
            uint2 bf[4];
            #pragma unroll
            for (int i = 0; i < 4; i++)
                af[i] = *(const uint4*)&As[((kb * 8 + warp_m * 4 + i) * 32 + lane) * 4];
            #pragma unroll
            for (int j = 0; j < 4; j++)
                bf[j] = *(const uint2*)&Bs[((kb * 16 + warp_n * 4 + j) * 32 + lane) * 2];
            #pragma unroll
            for (int i = 0; i < 4; i++)
                #pragma unroll
                for (int j = 0; j < 4; j++)
                    MMA_TF32(acc[i][j], af[i], bf[j]);
        }
    }

    int g  = lane >> 2;
    int t4 = lane & 3;
    #pragma unroll
    for (int i = 0; i < 4; i++) {
        int r0 = m0 + warp_m * 64 + i * 16 + g;
        #pragma unroll
        for (int j = 0; j < 4; j++) {
            int c0 = n0 + warp_n * 32 + j * 8 + t4 * 2;
            float bv0 = Bv[c0], bv1 = Bv[c0 + 1];
            float2 v0 = make_float2(acc[i][j][0] + bv0, acc[i][j][1] + bv1);
            float2 v1 = make_float2(acc[i][j][2] + bv0, acc[i][j][3] + bv1);
            if (headmode) {
                long hb = (long)(c0 >> 6) * T_TOT + toff;
                *(float2*)&Oo[(hb + r0) * 64 + (c0 & 63)]     = v0;
                *(float2*)&Oo[(hb + r0 + 8) * 64 + (c0 & 63)] = v1;
            } else {
                *(float2*)&Oo[(long)r0 * D_MODEL + c0]       = v0;
                *(float2*)&Oo[(long)(r0 + 8) * D_MODEL + c0] = v1;
            }
        }
    }
}

// ---------------------------------------------------------------------------
// Fused per-head RMSNorm over last dim (64). One warp per row.
// rows [0, NH*S_HID)            -> Q buffer, weight nq
// rows [NH*S_HID, +NH*T_TOT)    -> K buffer, weight nk (t<S_HID) else nak
// ---------------------------------------------------------------------------
__global__ void rmsnorm_kernel(float* __restrict__ bufQ, float* __restrict__ bufK,
                               const float* __restrict__ nq,
                               const float* __restrict__ nk,
                               const float* __restrict__ nak)
{
    const int rowsQ = NH * S_HID;
    const int nrows = rowsQ + NH * T_TOT;
    int row = blockIdx.x * (blockDim.x >> 5) + (threadIdx.x >> 5);
    if (row >= nrows) return;
    int lane = threadIdx.x & 31;

    float* p;
    const float* w;
    if (row < rowsQ) {
        int h = row / S_HID;
        int t = row - h * S_HID;
        p = bufQ + ((long)h * T_TOT + t) * HD;
        w = nq;
    } else {
        int idx = row - rowsQ;
        int h = idx / T_TOT;
        int t = idx - h * T_TOT;
        p = bufK + ((long)h * T_TOT + t) * HD;
        w = (t < S_HID) ? nk : nak;
    }
    p += lane * 2;
    float2 v = *(float2*)p;
    float ss = v.x * v.x + v.y * v.y;
    #pragma unroll
    for (int o = 16; o > 0; o >>= 1) ss += __shfl_xor_sync(0xffffffffu, ss, o);
    float inv = rsqrtf(ss * (1.0f / 64.0f) + 1e-6f);
    v.x *= inv * w[lane * 2];
    v.y *= inv * w[lane * 2 + 1];
    *(float2*)p = v;
}

// ---------------------------------------------------------------------------
// Split-TF32 tensor-core flash attention.
// 128 threads = 4 warps; warp w owns q-rows [q0+16w, q0+16w+16); BKV=32.
// QK^T uses 3-mma split-tf32 (hi*hi + lo*hi + hi*lo) to kill the tf32
// score error; PV stays single tf32. Q hi/lo fragments register-resident;
// K hi/lo and V^T scattered to fragment-major smem at load; P round-trips
// through per-warp fragment-major smem. Online softmax with quad shuffles.
// ---------------------------------------------------------------------------
__global__ __launch_bounds__(128, 2)
void attn_kernel(const float* __restrict__ Q, const float* __restrict__ K,
                 const float* __restrict__ V, const float* __restrict__ mask,
                 float* __restrict__ O)
{
    __shared__ uint32_t Ks[2048];    // hi: [kb(d)0..7][nt(kv)0..3][lane][2]
    __shared__ uint32_t Kl[2048];    // lo: same layout
    __shared__ uint32_t Vs[2048];    // [kb(kv)0..3][nt(d)0..7][lane][2]
    __shared__ uint32_t Ps[4][512];  // per warp: [kb(kv)0..3][lane][4]
    __shared__ float    Ms[T_TOT];

    int h   = blockIdx.y;
    int q0  = blockIdx.x * 64;
    int tid = threadIdx.x;
    int lane = tid & 31;
    int w    = tid >> 5;
    int g  = lane >> 2;
    int t4 = lane & 3;

    const float* Qh = Q + ((long)h * T_TOT + q0 + w * 16) * HD;
    const float* Kh = K + (long)h * T_TOT * HD;
    const float* Vh = V + (long)h * T_TOT * HD;

    for (int i = tid; i < T_TOT; i += 128) Ms[i] = mask[i];

    // Q hi/lo fragments (scale 1/8 is exact in fp32)
    uint4 qf[8], ql[8];
    #pragma unroll
    for (int kb = 0; kb < 8; kb++) {
        int c = kb * 8 + t4;
        float x0 = 0.125f * Qh[g * 64 + c];
        float x1 = 0.125f * Qh[(g + 8) * 64 + c];
        float x2 = 0.125f * Qh[g * 64 + c + 4];
        float x3 = 0.125f * Qh[(g + 8) * 64 + c + 4];
        qf[kb].x = f2tf(x0); ql[kb].x = f2tf(x0 - __uint_as_float(qf[kb].x));
        qf[kb].y = f2tf(x1); ql[kb].y = f2tf(x1 - __uint_as_float(qf[kb].y));
        qf[kb].z = f2tf(x2); ql[kb].z = f2tf(x2 - __uint_as_float(qf[kb].z));
        qf[kb].w = f2tf(x3); ql[kb].w = f2tf(x3 - __uint_as_float(qf[kb].w));
    }

    float oacc[8][4];
    #pragma unroll
    for (int nt = 0; nt < 8; nt++)
        #pragma unroll
        for (int e = 0; e < 4; e++) oacc[nt][e] = 0.f;
    float m0 = -1e30f, m1 = -1e30f, l0 = 0.f, l1 = 0.f;

    int lr = tid >> 2;          // kv row 0..31
    int dq = (tid & 3) * 16;    // d quarter

    float4 kp[4], vp[4];
    #pragma unroll
    for (int q = 0; q < 4; q++) {
        kp[q] = *(const float4*)(Kh + (long)lr * 64 + dq + q * 4);
        vp[q] = *(const float4*)(Vh + (long)lr * 64 + dq + q * 4);
    }

    for (int k0 = 0; k0 < T_TOT; k0 += 32) {
        __syncthreads();   // prev PV fragment reads complete
        #pragma unroll
        for (int q = 0; q < 4; q++) {
            #pragma unroll
            for (int j = 0; j < 4; j++) {
                int d = dq + q * 4 + j;
                float kv = ((const float*)&kp[q])[j];
                float vv = ((const float*)&vp[q])[j];
                int ki = (((d >> 3) * 4 + (lr >> 3)) * 32 + (lr & 7) * 4 + (d & 3)) * 2 + ((d >> 2) & 1);
                uint32_t khi = f2tf(kv);
                Ks[ki] = khi;
                Kl[ki] = f2tf(kv - __uint_as_float(khi));
                Vs[(((lr >> 3) * 8 + (d >> 3)) * 32 + (d & 7) * 4 + (lr & 3)) * 2 + ((lr >> 2) & 1)] = f2tf(vv);
            }
        }
        __syncthreads();

        if (k0 + 32 < T_TOT) {   // prefetch next K/V tile; overlaps compute
            #pragma unroll
            for (int q = 0; q < 4; q++) {
                kp[q] = *(const float4*)(Kh + (long)(k0 + 32 + lr) * 64 + dq + q * 4);
                vp[q] = *(const float4*)(Vh + (long)(k0 + 32 + lr) * 64 + dq + q * 4);
            }
        }

        // S = Q @ K^T  split-tf32: hi*hi + lo*hi + hi*lo
        float sacc[4][4];
        #pragma unroll
        for (int nt = 0; nt < 4; nt++)
            #pragma unroll
            for (int e = 0; e < 4; e++) sacc[nt][e] = 0.f;
        #pragma unroll
        for (int kb = 0; kb < 8; kb++)
            #pragma unroll
            for (int nt = 0; nt < 4; nt++) {
                int ki = ((kb * 4 + nt) * 32 + lane) * 2;
                uint2 bh = *(const uint2*)&Ks[ki];
                uint2 bl = *(const uint2*)&Kl[ki];
                MMA_TF32(sacc[nt], qf[kb], bh);
                MMA_TF32(sacc[nt], ql[kb], bh);
                MMA_TF32(sacc[nt], qf[kb], bl);
            }

        // mask + row max
        float rm0 = -1e30f, rm1 = -1e30f;
        #pragma unroll
        for (int nt = 0; nt < 4; nt++) {
            float2 mk = *(const float2*)&Ms[k0 + nt * 8 + 2 * t4];
            sacc[nt][0] += mk.x; sacc[nt][1] += mk.y;
            sacc[nt][2] += mk.x; sacc[nt][3] += mk.y;
            rm0 = fmaxf(rm0, fmaxf(sacc[nt][0], sacc[nt][1]));
            rm1 = fmaxf(rm1, fmaxf(sacc[nt][2], sacc[nt][3]));
        }
        #pragma unroll
        for (int o = 1; o <= 2; o <<= 1) {
            rm0 = fmaxf(rm0, __shfl_xor_sync(0xffffffffu, rm0, o));
            rm1 = fmaxf(rm1, __shfl_xor_sync(0xffffffffu, rm1, o));
        }
        float mn0 = fmaxf(m0, rm0), mn1 = fmaxf(m1, rm1);
        float c0 = __expf(m0 - mn0), c1 = __expf(m1 - mn1);

        // exp, row sums, write P fragments
        float rs0 = 0.f, rs1 = 0.f;
        #pragma unroll
        for (int nt = 0; nt < 4; nt++) {
            #pragma unroll
            for (int e = 0; e < 2; e++) {
                float p0 = __expf(sacc[nt][e]     - mn0);
                float p1 = __expf(sacc[nt][2 + e] - mn1);
                rs0 += p0; rs1 += p1;
                int cc  = 2 * t4 + e;
                int idx = (nt * 32 + g * 4 + (cc & 3)) * 4 + ((cc & 4) >> 1);
                Ps[w][idx]     = f2tf(p0);   // row g
                Ps[w][idx + 1] = f2tf(p1);   // row g+8
            }
        }
        #pragma unroll
        for (int o = 1; o <= 2; o <<= 1) {
            rs0 += __shfl_xor_sync(0xffffffffu, rs0, o);
            rs1 += __shfl_xor_sync(0xffffffffu, rs1, o);
        }
        l0 = l0 * c0 + rs0;  m0 = mn0;
        l1 = l1 * c1 + rs1;  m1 = mn1;
        #pragma unroll
        for (int nt = 0; nt < 8; nt++) {
            oacc[nt][0] *= c0; oacc[nt][1] *= c0;
            oacc[nt][2] *= c1; oacc[nt][3] *= c1;
        }
        __syncwarp();

        // O += P @ V
        #pragma unroll
        for (int kb = 0; kb < 4; kb++) {
            uint4 pf = *(const uint4*)&Ps[w][(kb * 32 + lane) * 4];
            #pragma unroll
            for (int nt = 0; nt < 8; nt++) {
                uint2 bf = *(const uint2*)&Vs[((kb * 8 + nt) * 32 + lane) * 2];
                MMA_TF32(oacc[nt], pf, bf);
            }
        }
    }

    float i0 = 1.f / l0, i1 = 1.f / l1;
    int r0 = q0 + w * 16 + g;
    #pragma unroll
    for (int nt = 0; nt < 8; nt++) {
        int c = h * 64 + nt * 8 + 2 * t4;
        *(float2*)&O[(long)r0 * D_MODEL + c]       = make_float2(oacc[nt][0] * i0, oacc[nt][1] * i0);
        *(float2*)&O[(long)(r0 + 8) * D_MODEL + c] = make_float2(oacc[nt][2] * i1, oacc[nt][3] * i1);
    }
}

// ---------------------------------------------------------------------------
extern "C" void kernel_launch(void* const* d_in, const int* in_sizes, int n_in,
                              void* d_out, int out_size)
{
    const float* hid  = (const float*)d_in[0];
    const float* enc  = (const float*)d_in[1];
    const float* mask = (const float*)d_in[2];
    const float* Wq   = (const float*)d_in[3];
    const float* bq   = (const float*)d_in[4];
    const float* Wk   = (const float*)d_in[5];
    const float* bk   = (const float*)d_in[6];
    const float* Wv   = (const float*)d_in[7];
    const float* bv   = (const float*)d_in[8];
    const float* nq   = (const float*)d_in[9];
    const float* nk   = (const float*)d_in[10];
    // d_in[11], d_in[12]: add_q_proj (dead: encoder queries' output is discarded)
    const float* Wak  = (const float*)d_in[13];
    const float* bak  = (const float*)d_in[14];
    const float* Wav  = (const float*)d_in[15];
    const float* bav  = (const float*)d_in[16];
    // d_in[17]: norm_added_q (dead)
    const float* nak  = (const float*)d_in[18];
    const float* Wo   = (const float*)d_in[19];
    const float* bo   = (const float*)d_in[20];
    // d_in[21], d_in[22]: to_add_out (dead), d_in[23], d_in[24]: scalars
    float* out = (float*)d_out;

    float *Qb, *Kb, *Vb, *Ob;
    cudaGetSymbolAddress((void**)&Qb, g_Q);
    cudaGetSymbolAddress((void**)&Kb, g_K);
    cudaGetSymbolAddress((void**)&Vb, g_V);
    cudaGetSymbolAddress((void**)&Ob, g_O);

    // 1) all QKV projections (hidden QKV + encoder KV) in one launch
    {
        dim3 grid(D_MODEL / 128, S_HID / 128, 5);
        gemm_kernel<<<grid, 256>>>(hid, enc,
                                   Wq, bq, Qb,
                                   Wk, bk, Kb,
                                   Wv, bv, Vb,
                                   Wak, bak, Kb,
                                   Wav, bav, Vb,
                                   1);
    }
    // 2) fused RMSNorm on Q (hidden) and K (hidden + encoder)
    {
        int nrows = NH * S_HID + NH * T_TOT;
        rmsnorm_kernel<<<(nrows + 7) / 8, 256>>>(Qb, Kb, nq, nk, nak);
    }
    // 3) attention (2048 queries x 2304 keys, 24 heads) — split-tf32 QK^T
    {
        dim3 grid(S_HID / 64, NH);
        attn_kernel<<<grid, 128>>>(Qb, Kb, Vb, mask, Ob);
    }
    // 4) output projection -> d_out
    {
        dim3 grid(D_MODEL / 128, S_HID / 128, 1);
        gemm_kernel<<<grid, 256>>>(Ob, Ob,
                                   Wo, bo, out,
                                   Wo, bo, out,   // unused slots
                                   Wo, bo, out,
                                   Wo, bo, out,
                                   Wo, bo, out,
                                   0);
    }
}